// round 14
// baseline (speedup 1.0000x reference)
#include <cuda_runtime.h>
#include <cuda_fp16.h>
#include <math.h>
#include <stdint.h>

#define B_      4096
#define SEQ_    59
#define FEAT_   64
#define U_      1024
#define VOCAB_  578
#define NPAD    640
#define KTOT    1088            // U_ + FEAT_
#define N4U     4096            // 4*U_
#define XROW    (SEQ_*FEAT_)

#define KBLK        64
#define NKB         17          // KTOT / KBLK
#define NSTAGE      3
#define STAGE_BYTES 32768       // A 16K | B 16K
#define SMEM_BYTES  (NSTAGE * STAGE_BYTES)   // 98304 per CTA, 2 CTAs/SM
#define NCTA        296         // 2 x 148: all co-resident
#define NTILES      1024        // 32 mgroups x 32 ntiles

// ---------------- device scratch ----------------
__device__ __half g_Wt[(size_t)N4U * KTOT];      // [n][k], n = 4u+g permuted
__device__ float  g_biasp[N4U];
__device__ __half g_h16[2][(size_t)B_ * U_];
__device__ float  g_c[(size_t)B_ * U_];
__device__ __half g_x16[(size_t)SEQ_ * B_ * FEAT_]; // [t][b][f]
__device__ float  g_w2p[U_ * NPAD];
__device__ float  g_b2p[NPAD];
__device__ float  g_logits[(size_t)B_ * NPAD];
__device__ int    g_flag[SEQ_ * 32 * 32];        // per (t, mgroup, ntile)

// ---------------- helpers ----------------
__device__ __forceinline__ uint32_t s2u(const void* p) {
    uint32_t a;
    asm("{ .reg .u64 t; cvta.to.shared.u64 t, %1; cvt.u32.u64 %0, t; }"
        : "=r"(a) : "l"(p));
    return a;
}
__device__ __forceinline__ void cp16(uint32_t saddr, const void* g) {
    asm volatile("cp.async.cg.shared.global [%0], [%1], 16;"
                 :: "r"(saddr), "l"(g));
}
__device__ __forceinline__ void ldmx4(uint32_t* r, uint32_t addr) {
    asm volatile("ldmatrix.sync.aligned.m8n8.x4.shared.b16 {%0,%1,%2,%3}, [%4];"
                 : "=r"(r[0]), "=r"(r[1]), "=r"(r[2]), "=r"(r[3]) : "r"(addr));
}
__device__ __forceinline__ void mma_f16(float* d, const uint32_t* a,
                                        const uint32_t* b) {
    asm volatile(
        "mma.sync.aligned.m16n8k16.row.col.f32.f16.f16.f32 "
        "{%0,%1,%2,%3}, {%4,%5,%6,%7}, {%8,%9}, {%0,%1,%2,%3};"
        : "+f"(d[0]), "+f"(d[1]), "+f"(d[2]), "+f"(d[3])
        : "r"(a[0]), "r"(a[1]), "r"(a[2]), "r"(a[3]), "r"(b[0]), "r"(b[1]));
}
#define SWZ(o) ((o) ^ (((o) >> 3) & 0x70))

__device__ __forceinline__ float fast_sigmoid(float x) {
    return __fdividef(1.f, 1.f + __expf(-x));
}
__device__ __forceinline__ float fast_tanh(float x) {
    float e = __expf(2.f * x);
    return 1.f - __fdividef(2.f, e + 1.f);
}
__device__ __forceinline__ void wait_flag(const int* p) {
    int v;
    do {
        asm volatile("ld.acquire.gpu.global.s32 %0, [%1];"
                     : "=r"(v) : "l"(p) : "memory");
        if (!v) __nanosleep(32);
    } while (!v);
}

// ---------------- prep kernels ----------------
__global__ void prep_weights(const float* __restrict__ kernel,
                             const float* __restrict__ rec,
                             const float* __restrict__ bias,
                             const float* __restrict__ w2,
                             const float* __restrict__ b2) {
    int stride = gridDim.x * blockDim.x;
    int idx = blockIdx.x * blockDim.x + threadIdx.x;
    for (size_t i = idx; i < (size_t)N4U * KTOT; i += stride) {
        int n = (int)(i / KTOT), k = (int)(i % KTOT);
        int u = n >> 2, g = n & 3;
        int src = g * U_ + u;
        float v = (k < U_) ? rec[(size_t)k * N4U + src]
                           : kernel[(size_t)(k - U_) * N4U + src];
        g_Wt[i] = __float2half(v);
    }
    for (int n = idx; n < N4U; n += stride) {
        int u = n >> 2, g = n & 3;
        g_biasp[n] = bias[g * U_ + u];
    }
    for (int i = idx; i < U_ * NPAD; i += stride) {
        int k = i / NPAD, v = i - k * NPAD;
        g_w2p[i] = (v < VOCAB_) ? w2[k * VOCAB_ + v] : 0.f;
    }
    for (int v = idx; v < NPAD; v += stride)
        g_b2p[v] = (v < VOCAB_) ? b2[v] : 0.f;
}

__global__ void prep_x(const float* __restrict__ x) {
    int stride = gridDim.x * blockDim.x;
    int idx = blockIdx.x * blockDim.x + threadIdx.x;
    for (size_t i = idx; i < (size_t)SEQ_ * B_ * FEAT_; i += stride) {
        int t = (int)(i / ((size_t)B_ * FEAT_));
        int r = (int)((i / FEAT_) % B_);
        int f = (int)(i % FEAT_);
        g_x16[i] = __float2half(x[(size_t)r * XROW + t * FEAT_ + f]);
    }
}

__global__ void zero_state() {
    int stride = gridDim.x * blockDim.x;
    int idx = blockIdx.x * blockDim.x + threadIdx.x;
    const __half z = __float2half(0.f);
    for (size_t i = idx; i < (size_t)B_ * U_; i += stride) {
        g_h16[0][i] = z;
        g_c[i] = 0.f;
    }
    for (int i = idx; i < SEQ_ * 32 * 32; i += stride)
        g_flag[i] = 0;
}

// ---------------- persistent LSTM: all 59 steps, fine-grained deps -------
// CTA 128x128, 8 warps (2M x 4N), warp tile 64x32, K-chunk 64,
// 3-stage cp.async, per-warp kk rotation, 296 CTAs (2/SM, all resident).
// K-block order: x-block (16) first, then h-blocks 0..15. h-block kb only
// needs producer tiles (t-1, mg, 2kb) and (2kb+1): per-tile flags checked
// just before each prefetch. Epilogue publishes this tile's flag.
__global__ void __launch_bounds__(256, 2)
lstm_persistent() {
    extern __shared__ __align__(1024) char smem[];
    const uint32_t sb = s2u(smem);
    const int tid = threadIdx.x;
    const int lane = tid & 31, wid = tid >> 5;
    const int wm = wid & 1, wn = wid >> 1;

    const int arow = wm * 64 + (lane & 15);
    const int brow = wn * 32 + (lane & 7) + ((lane >> 4) & 1) * 8;

    #pragma unroll 1
    for (int t = 0; t < SEQ_; t++) {
        const __half* __restrict__ hh = g_h16[t & 1];
        __half* __restrict__ oh = g_h16[(t & 1) ^ 1];

        #pragma unroll 1
        for (int idx = blockIdx.x; idx < NTILES; idx += NCTA) {
            const int mg = idx >> 5;
            const int mbase = mg * 128;
            const int nbase = (idx & 31) * 128;
            const int* fbase = (t > 0) ? &g_flag[(((t - 1) << 5) + mg) << 5]
                                       : (const int*)0;

            float acc[4][4][4];
            #pragma unroll
            for (int i = 0; i < 4; i++)
                #pragma unroll
                for (int j = 0; j < 4; j++)
                    #pragma unroll
                    for (int q = 0; q < 4; q++) acc[i][j][q] = 0.f;

            auto loadStage = [&](int s, int kb) {
                const uint32_t base = sb + s * STAGE_BYTES;
                #pragma unroll
                for (int it = 0; it < 4; it++) {
                    int i2 = tid + it * 256;
                    int row = i2 >> 3, cc = i2 & 7;
                    uint32_t sw = SWZ((uint32_t)(row * 128 + cc * 16));
                    const __half* ga;
                    if (kb < 16)
                        ga = hh + (size_t)(mbase + row) * U_ + kb * KBLK + cc * 8;
                    else
                        ga = g_x16 + ((size_t)t * B_ + mbase + row) * FEAT_ + cc * 8;
                    cp16(base + sw, ga);
                    size_t ob = (size_t)(nbase + row) * KTOT + kb * KBLK + cc * 8;
                    cp16(base + 16384 + sw, g_Wt + ob);
                }
                asm volatile("cp.async.commit_group;" ::: "memory");
            };

            // prologue: x block (no dep), then h block 0 (deps: tiles 0,1)
            loadStage(0, 16);
            if (fbase) { wait_flag(fbase + 0); wait_flag(fbase + 1); }
            loadStage(1, 0);

            #pragma unroll 1
            for (int j = 0; j < NKB; j++) {
                if (j < NKB - 1) asm volatile("cp.async.wait_group 1;" ::: "memory");
                else            asm volatile("cp.async.wait_group 0;" ::: "memory");
                __syncthreads();

                // prefetch h block (j+1) into stage (j+2)%3; deps 2(j+1),2(j+1)+1
                if (j + 2 <= 16) {
                    const int nk = j + 1;       // h block 1..15
                    if (fbase) {
                        wait_flag(fbase + 2 * nk);
                        wait_flag(fbase + 2 * nk + 1);
                    }
                    loadStage((j + 2) % 3, nk);
                }

                const uint32_t Ab = sb + (j % 3) * STAGE_BYTES;
                const uint32_t Bb = Ab + 16384;

                #pragma unroll
                for (int kx = 0; kx < 4; kx++) {
                    const int kk = (kx + wid) & 3;   // per-warp phase rotation
                    uint32_t af[4][4], bf[2][4];
                    const uint32_t akoff = (uint32_t)(kk * 32 + ((lane >> 4) & 1) * 16);
                    #pragma unroll
                    for (int mt = 0; mt < 4; mt++)
                        ldmx4(af[mt], Ab + SWZ((uint32_t)((arow + mt * 16) * 128) + akoff));
                    const uint32_t bkoff = (uint32_t)(kk * 32 + ((lane >> 3) & 1) * 16);
                    #pragma unroll
                    for (int np = 0; np < 2; np++)
                        ldmx4(bf[np], Bb + SWZ((uint32_t)((brow + np * 16) * 128) + bkoff));
                    #pragma unroll
                    for (int mt = 0; mt < 4; mt++)
                        #pragma unroll
                        for (int nt = 0; nt < 4; nt++)
                            mma_f16(acc[mt][nt], af[mt], &bf[nt >> 1][(nt & 1) * 2]);
                }
            }
            __syncthreads();

            // ---- epilogue: stage accums to smem [128][132], gate math ----
            float* sf = reinterpret_cast<float*>(smem);
            #pragma unroll
            for (int mt = 0; mt < 4; mt++) {
                int r0 = wm * 64 + mt * 16 + (lane >> 2);
                #pragma unroll
                for (int nt = 0; nt < 4; nt++) {
                    int c = wn * 32 + nt * 8 + 2 * (lane & 3);
                    sf[r0 * 132 + c]           = acc[mt][nt][0];
                    sf[r0 * 132 + c + 1]       = acc[mt][nt][1];
                    sf[(r0 + 8) * 132 + c]     = acc[mt][nt][2];
                    sf[(r0 + 8) * 132 + c + 1] = acc[mt][nt][3];
                }
            }
            __syncthreads();

            #pragma unroll 1
            for (int it = 0; it < 16; it++) {
                int i2 = it * 256 + tid;
                int row = i2 >> 5, uu = i2 & 31;
                float4 z = *reinterpret_cast<const float4*>(&sf[row * 132 + uu * 4]);
                int n0 = nbase + uu * 4;
                float4 bz = *reinterpret_cast<const float4*>(&g_biasp[n0]);
                float ig = fast_sigmoid(z.x + bz.x);
                float fg = fast_sigmoid(z.y + bz.y);
                float gg = fast_tanh(z.z + bz.z);
                float og = fast_sigmoid(z.w + bz.w);
                size_t ci = (size_t)(mbase + row) * U_ + (n0 >> 2);
                float cn = fg * g_c[ci] + ig * gg;
                g_c[ci] = cn;
                float hv = og * fast_tanh(cn);
                oh[ci] = __float2half(hv);
            }

            // ---- publish this tile's flag (release) ----
            __syncthreads();
            if (tid == 0) {
                __threadfence();
                int* fp = &g_flag[((t << 5) + mg) * 32 + (idx & 31)];
                asm volatile("st.release.gpu.global.s32 [%0], %1;"
                             :: "l"(fp), "r"(1) : "memory");
            }
        }
    }
}

// ---------------- final dense (fp32 SGEMM on fp16 h) ----------------
__global__ void __launch_bounds__(256, 2)
dense2(int h_idx) {
    const __half* __restrict__ A = g_h16[h_idx];

    __shared__ __align__(16) float As[8][128];
    __shared__ __align__(16) float Bs[8][128];

    const int tid = threadIdx.x;
    const int tx = tid & 15, ty = tid >> 4;
    const int mbase = blockIdx.y * 128, nbase = blockIdx.x * 128;

    float acc[8][8];
    #pragma unroll
    for (int i = 0; i < 8; i++)
        #pragma unroll
        for (int j = 0; j < 8; j++) acc[i][j] = 0.f;

    const int arow = tid >> 1, acol = (tid & 1) << 2;
    const int brow = tid >> 5, bcol = (tid & 31) << 2;

    for (int k0 = 0; k0 < U_; k0 += 8) {
        size_t ao = (size_t)(mbase + arow) * U_ + k0 + acol;
        __half2 a01 = *reinterpret_cast<const __half2*>(A + ao);
        __half2 a23 = *reinterpret_cast<const __half2*>(A + ao + 2);
        float2 f01 = __half22float2(a01);
        float2 f23 = __half22float2(a23);
        As[acol + 0][arow] = f01.x;
        As[acol + 1][arow] = f01.y;
        As[acol + 2][arow] = f23.x;
        As[acol + 3][arow] = f23.y;

        float4 bv = *reinterpret_cast<const float4*>(
            g_w2p + (size_t)(k0 + brow) * NPAD + nbase + bcol);
        *reinterpret_cast<float4*>(&Bs[brow][bcol]) = bv;

        __syncthreads();
        #pragma unroll
        for (int kk = 0; kk < 8; kk++) {
            float a[8], b[8];
            const float4* Av = reinterpret_cast<const float4*>(&As[kk][ty * 8]);
            const float4* Bv = reinterpret_cast<const float4*>(&Bs[kk][tx * 8]);
            float4 a0 = Av[0], a1 = Av[1], b0 = Bv[0], b1 = Bv[1];
            a[0]=a0.x;a[1]=a0.y;a[2]=a0.z;a[3]=a0.w;a[4]=a1.x;a[5]=a1.y;a[6]=a1.z;a[7]=a1.w;
            b[0]=b0.x;b[1]=b0.y;b[2]=b0.z;b[3]=b0.w;b[4]=b1.x;b[5]=b1.y;b[6]=b1.z;b[7]=b1.w;
            #pragma unroll
            for (int i = 0; i < 8; i++)
                #pragma unroll
                for (int j = 0; j < 8; j++)
                    acc[i][j] = fmaf(a[i], b[j], acc[i][j]);
        }
        __syncthreads();
    }
    #pragma unroll
    for (int i = 0; i < 8; i++) {
        int bi = mbase + ty * 8 + i;
        #pragma unroll
        for (int j = 0; j < 8; j++) {
            int n = nbase + tx * 8 + j;
            g_logits[(size_t)bi * NPAD + n] = acc[i][j] + g_b2p[n];
        }
    }
}

// ---------------- softmax ----------------
__global__ void softmax_kernel(float* __restrict__ out) {
    const int b = blockIdx.x;
    const float* __restrict__ l = g_logits + (size_t)b * NPAD;
    __shared__ float red[256];
    const int tid = threadIdx.x;

    float mval = -1e30f;
    for (int v = tid; v < VOCAB_; v += 256) mval = fmaxf(mval, l[v]);
    red[tid] = mval;
    __syncthreads();
    for (int s = 128; s > 0; s >>= 1) {
        if (tid < s) red[tid] = fmaxf(red[tid], red[tid + s]);
        __syncthreads();
    }
    float mx = red[0];
    __syncthreads();

    float sum = 0.f;
    for (int v = tid; v < VOCAB_; v += 256) sum += expf(l[v] - mx);
    red[tid] = sum;
    __syncthreads();
    for (int s = 128; s > 0; s >>= 1) {
        if (tid < s) red[tid] += red[tid + s];
        __syncthreads();
    }
    float inv = 1.f / red[0];
    for (int v = tid; v < VOCAB_; v += 256)
        out[(size_t)b * VOCAB_ + v] = expf(l[v] - mx) * inv;
}

// ---------------- launch ----------------
extern "C" void kernel_launch(void* const* d_in, const int* in_sizes, int n_in,
                              void* d_out, int out_size) {
    const float* x      = (const float*)d_in[0];
    const float* kernel = (const float*)d_in[1];
    const float* rec    = (const float*)d_in[2];
    const float* bias   = (const float*)d_in[3];
    const float* w2     = (const float*)d_in[4];
    const float* b2     = (const float*)d_in[5];
    float* out = (float*)d_out;

    cudaFuncSetAttribute(lstm_persistent,
                         cudaFuncAttributeMaxDynamicSharedMemorySize, SMEM_BYTES);

    prep_weights<<<2048, 256>>>(kernel, rec, bias, w2, b2);
    prep_x<<<2048, 256>>>(x);
    zero_state<<<2048, 256>>>();

    lstm_persistent<<<NCTA, 256, SMEM_BYTES>>>();

    dense2<<<dim3(NPAD / 128, B_ / 128), 256>>>(SEQ_ & 1);
    softmax_kernel<<<B_, 256>>>(out);
}

// round 15
// speedup vs baseline: 1.1707x; 1.1707x over previous
#include <cuda_runtime.h>
#include <cuda_fp16.h>
#include <math.h>
#include <stdint.h>

#define B_      4096
#define SEQ_    59
#define FEAT_   64
#define U_      1024
#define VOCAB_  578
#define NPAD    640
#define KTOT    1088            // U_ + FEAT_
#define N4U     4096            // 4*U_
#define XROW    (SEQ_*FEAT_)

#define KBLK        64
#define NKB         17          // KTOT / KBLK
#define NSTAGE      3
#define STAGE_BYTES 32768       // A 16K | B 16K
#define SMEM_BYTES  (NSTAGE * STAGE_BYTES)   // 98304 per CTA, 2 CTAs/SM
#define NCTA        296         // 2 x 148: all co-resident
#define NTILES      1024        // 32 mgroups x 32 ntiles

// ---------------- device scratch ----------------
__device__ __half g_Wt[(size_t)N4U * KTOT];      // [n][k], n = 4u+g permuted
__device__ float  g_biasp[N4U];
__device__ __half g_h16[2][(size_t)B_ * U_];
__device__ float  g_c[(size_t)B_ * U_];
__device__ __half g_x16[(size_t)SEQ_ * B_ * FEAT_]; // [t][b][f]
__device__ __half g_w2t[(size_t)NPAD * U_];      // [n][k] fp16
__device__ float  g_b2p[NPAD];
__device__ float  g_logits[(size_t)B_ * NPAD];
__device__ int    g_cnt[SEQ_ * 32];              // per (t, mgroup) finished n-tiles

// ---------------- helpers ----------------
__device__ __forceinline__ uint32_t s2u(const void* p) {
    uint32_t a;
    asm("{ .reg .u64 t; cvta.to.shared.u64 t, %1; cvt.u32.u64 %0, t; }"
        : "=r"(a) : "l"(p));
    return a;
}
__device__ __forceinline__ void cp16(uint32_t saddr, const void* g) {
    asm volatile("cp.async.cg.shared.global [%0], [%1], 16;"
                 :: "r"(saddr), "l"(g));
}
__device__ __forceinline__ void ldmx4(uint32_t* r, uint32_t addr) {
    asm volatile("ldmatrix.sync.aligned.m8n8.x4.shared.b16 {%0,%1,%2,%3}, [%4];"
                 : "=r"(r[0]), "=r"(r[1]), "=r"(r[2]), "=r"(r[3]) : "r"(addr));
}
__device__ __forceinline__ void mma_f16(float* d, const uint32_t* a,
                                        const uint32_t* b) {
    asm volatile(
        "mma.sync.aligned.m16n8k16.row.col.f32.f16.f16.f32 "
        "{%0,%1,%2,%3}, {%4,%5,%6,%7}, {%8,%9}, {%0,%1,%2,%3};"
        : "+f"(d[0]), "+f"(d[1]), "+f"(d[2]), "+f"(d[3])
        : "r"(a[0]), "r"(a[1]), "r"(a[2]), "r"(a[3]), "r"(b[0]), "r"(b[1]));
}
#define SWZ(o) ((o) ^ (((o) >> 3) & 0x70))

__device__ __forceinline__ float fast_sigmoid(float x) {
    return __fdividef(1.f, 1.f + __expf(-x));
}
__device__ __forceinline__ float fast_tanh(float x) {
    float e = __expf(2.f * x);
    return 1.f - __fdividef(2.f, e + 1.f);
}

// ---------------- prep kernels ----------------
__global__ void prep_weights(const float* __restrict__ kernel,
                             const float* __restrict__ rec,
                             const float* __restrict__ bias,
                             const float* __restrict__ w2,
                             const float* __restrict__ b2) {
    int stride = gridDim.x * blockDim.x;
    int idx = blockIdx.x * blockDim.x + threadIdx.x;
    for (size_t i = idx; i < (size_t)N4U * KTOT; i += stride) {
        int n = (int)(i / KTOT), k = (int)(i % KTOT);
        int u = n >> 2, g = n & 3;
        int src = g * U_ + u;
        float v = (k < U_) ? rec[(size_t)k * N4U + src]
                           : kernel[(size_t)(k - U_) * N4U + src];
        g_Wt[i] = __float2half(v);
    }
    for (int n = idx; n < N4U; n += stride) {
        int u = n >> 2, g = n & 3;
        g_biasp[n] = bias[g * U_ + u];
    }
    // w2 transposed fp16: [NPAD][U_]
    for (size_t i = idx; i < (size_t)NPAD * U_; i += stride) {
        int n = (int)(i / U_), k = (int)(i % U_);
        g_w2t[i] = __float2half((n < VOCAB_) ? w2[(size_t)k * VOCAB_ + n] : 0.f);
    }
    for (int v = idx; v < NPAD; v += stride)
        g_b2p[v] = (v < VOCAB_) ? b2[v] : 0.f;
}

__global__ void prep_x(const float* __restrict__ x) {
    int stride = gridDim.x * blockDim.x;
    int idx = blockIdx.x * blockDim.x + threadIdx.x;
    for (size_t i = idx; i < (size_t)SEQ_ * B_ * FEAT_; i += stride) {
        int t = (int)(i / ((size_t)B_ * FEAT_));
        int r = (int)((i / FEAT_) % B_);
        int f = (int)(i % FEAT_);
        g_x16[i] = __float2half(x[(size_t)r * XROW + t * FEAT_ + f]);
    }
}

__global__ void zero_state() {
    int stride = gridDim.x * blockDim.x;
    int idx = blockIdx.x * blockDim.x + threadIdx.x;
    const __half z = __float2half(0.f);
    for (size_t i = idx; i < (size_t)B_ * U_; i += stride) {
        g_h16[0][i] = z;
        g_c[i] = 0.f;
    }
    for (int i = idx; i < SEQ_ * 32; i += stride)
        g_cnt[i] = 0;
}

// ---------------- persistent LSTM: all 59 steps in one kernel -------------
// CTA 128x128, 8 warps (2M x 4N), warp tile 64x32, K-chunk 64,
// 3-stage cp.async, per-warp kk rotation, 296 CTAs (2/SM, all resident).
// K-block order: x-block first (no dep), coarse per-(t,mg) counter wait
// overlapped behind the x prefetch, then h-blocks 0..15.
__global__ void __launch_bounds__(256, 2)
lstm_persistent() {
    extern __shared__ __align__(1024) char smem[];
    const uint32_t sb = s2u(smem);
    const int tid = threadIdx.x;
    const int lane = tid & 31, wid = tid >> 5;
    const int wm = wid & 1, wn = wid >> 1;

    const int arow = wm * 64 + (lane & 15);
    const int brow = wn * 32 + (lane & 7) + ((lane >> 4) & 1) * 8;

    #pragma unroll 1
    for (int t = 0; t < SEQ_; t++) {
        const __half* __restrict__ hh = g_h16[t & 1];
        __half* __restrict__ oh = g_h16[(t & 1) ^ 1];

        #pragma unroll 1
        for (int idx = blockIdx.x; idx < NTILES; idx += NCTA) {
            const int mg = idx >> 5;
            const int mbase = mg * 128;
            const int nbase = (idx & 31) * 128;

            float acc[4][4][4];
            #pragma unroll
            for (int i = 0; i < 4; i++)
                #pragma unroll
                for (int j = 0; j < 4; j++)
                    #pragma unroll
                    for (int q = 0; q < 4; q++) acc[i][j][q] = 0.f;

            auto loadStage = [&](int s, int kb) {
                const uint32_t base = sb + s * STAGE_BYTES;
                #pragma unroll
                for (int it = 0; it < 4; it++) {
                    int i2 = tid + it * 256;
                    int row = i2 >> 3, cc = i2 & 7;
                    uint32_t sw = SWZ((uint32_t)(row * 128 + cc * 16));
                    const __half* ga;
                    if (kb < 16)
                        ga = hh + (size_t)(mbase + row) * U_ + kb * KBLK + cc * 8;
                    else
                        ga = g_x16 + ((size_t)t * B_ + mbase + row) * FEAT_ + cc * 8;
                    cp16(base + sw, ga);
                    size_t ob = (size_t)(nbase + row) * KTOT + kb * KBLK + cc * 8;
                    cp16(base + 16384 + sw, g_Wt + ob);
                }
                asm volatile("cp.async.commit_group;" ::: "memory");
            };

            // prologue: x block first (no cross-step dep) ...
            loadStage(0, 16);
            // ... then the coarse wait, overlapped behind the x prefetch
            if (t > 0) {
                if (tid == 0) {
                    const int* cp = &g_cnt[(t - 1) * 32 + mg];
                    int v;
                    do {
                        asm volatile("ld.acquire.gpu.global.s32 %0, [%1];"
                                     : "=r"(v) : "l"(cp) : "memory");
                        if (v < 32) __nanosleep(64);
                    } while (v < 32);
                }
                __syncthreads();
            }
            loadStage(1, 0);

            // j-th compute block: kb = (j==0) ? 16 : j-1
            #pragma unroll 1
            for (int j = 0; j < NKB; j++) {
                if (j < NKB - 1) asm volatile("cp.async.wait_group 1;" ::: "memory");
                else            asm volatile("cp.async.wait_group 0;" ::: "memory");
                __syncthreads();

                // prefetch block j+2 (kb = j+1) into stage (j+2)%3
                if (j + 2 < NKB) loadStage((j + 2) % 3, j + 1);

                const uint32_t Ab = sb + (j % 3) * STAGE_BYTES;
                const uint32_t Bb = Ab + 16384;

                #pragma unroll
                for (int kx = 0; kx < 4; kx++) {
                    const int kk = (kx + wid) & 3;   // per-warp phase rotation
                    uint32_t af[4][4], bf[2][4];
                    const uint32_t akoff = (uint32_t)(kk * 32 + ((lane >> 4) & 1) * 16);
                    #pragma unroll
                    for (int mt = 0; mt < 4; mt++)
                        ldmx4(af[mt], Ab + SWZ((uint32_t)((arow + mt * 16) * 128) + akoff));
                    const uint32_t bkoff = (uint32_t)(kk * 32 + ((lane >> 3) & 1) * 16);
                    #pragma unroll
                    for (int np = 0; np < 2; np++)
                        ldmx4(bf[np], Bb + SWZ((uint32_t)((brow + np * 16) * 128) + bkoff));
                    #pragma unroll
                    for (int mt = 0; mt < 4; mt++)
                        #pragma unroll
                        for (int nt = 0; nt < 4; nt++)
                            mma_f16(acc[mt][nt], af[mt], &bf[nt >> 1][(nt & 1) * 2]);
                }
            }
            __syncthreads();

            // ---- epilogue: stage accums to smem [128][132], gate math ----
            float* sf = reinterpret_cast<float*>(smem);
            #pragma unroll
            for (int mt = 0; mt < 4; mt++) {
                int r0 = wm * 64 + mt * 16 + (lane >> 2);
                #pragma unroll
                for (int nt = 0; nt < 4; nt++) {
                    int c = wn * 32 + nt * 8 + 2 * (lane & 3);
                    sf[r0 * 132 + c]           = acc[mt][nt][0];
                    sf[r0 * 132 + c + 1]       = acc[mt][nt][1];
                    sf[(r0 + 8) * 132 + c]     = acc[mt][nt][2];
                    sf[(r0 + 8) * 132 + c + 1] = acc[mt][nt][3];
                }
            }
            __syncthreads();

            #pragma unroll 1
            for (int it = 0; it < 16; it++) {
                int i2 = it * 256 + tid;
                int row = i2 >> 5, uu = i2 & 31;
                float4 z = *reinterpret_cast<const float4*>(&sf[row * 132 + uu * 4]);
                int n0 = nbase + uu * 4;
                float4 bz = *reinterpret_cast<const float4*>(&g_biasp[n0]);
                float ig = fast_sigmoid(z.x + bz.x);
                float fg = fast_sigmoid(z.y + bz.y);
                float gg = fast_tanh(z.z + bz.z);
                float og = fast_sigmoid(z.w + bz.w);
                size_t ci = (size_t)(mbase + row) * U_ + (n0 >> 2);
                float cn = fg * g_c[ci] + ig * gg;
                g_c[ci] = cn;
                float hv = og * fast_tanh(cn);
                oh[ci] = __float2half(hv);
            }

            // ---- publish: release-add this tile to (t, mg) counter ----
            __syncthreads();
            if (tid == 0) {
                __threadfence();
                atomicAdd(&g_cnt[t * 32 + mg], 1);
            }
        }
    }
}

// ---------------- final dense: fp16 mma GEMM, logits = h @ w2 + b2 --------
// Same tile structure as lstm: CTA 128x128, 8 warps, K=1024 (16 blocks).
__global__ void __launch_bounds__(256, 2)
dense2_mma(int h_idx) {
    extern __shared__ __align__(1024) char smem[];
    const uint32_t sb = s2u(smem);
    const int tid = threadIdx.x;
    const int lane = tid & 31, wid = tid >> 5;
    const int wm = wid & 1, wn = wid >> 1;
    const int mbase = blockIdx.y * 128;
    const int nbase = blockIdx.x * 128;

    const __half* __restrict__ A = g_h16[h_idx];

    float acc[4][4][4];
    #pragma unroll
    for (int i = 0; i < 4; i++)
        #pragma unroll
        for (int j = 0; j < 4; j++)
            #pragma unroll
            for (int q = 0; q < 4; q++) acc[i][j][q] = 0.f;

    auto loadStage = [&](int s, int kb) {
        const uint32_t base = sb + s * STAGE_BYTES;
        #pragma unroll
        for (int it = 0; it < 4; it++) {
            int i2 = tid + it * 256;
            int row = i2 >> 3, cc = i2 & 7;
            uint32_t sw = SWZ((uint32_t)(row * 128 + cc * 16));
            cp16(base + sw, A + (size_t)(mbase + row) * U_ + kb * KBLK + cc * 8);
            cp16(base + 16384 + sw,
                 g_w2t + (size_t)(nbase + row) * U_ + kb * KBLK + cc * 8);
        }
        asm volatile("cp.async.commit_group;" ::: "memory");
    };

    loadStage(0, 0);
    loadStage(1, 1);

    const int arow = wm * 64 + (lane & 15);
    const int brow = wn * 32 + (lane & 7) + ((lane >> 4) & 1) * 8;

    const int NKD = U_ / KBLK;   // 16
    #pragma unroll 1
    for (int kb = 0; kb < NKD; kb++) {
        const int s = kb % 3;
        if (kb < NKD - 1) asm volatile("cp.async.wait_group 1;" ::: "memory");
        else             asm volatile("cp.async.wait_group 0;" ::: "memory");
        __syncthreads();

        if (kb + 2 < NKD) loadStage((kb + 2) % 3, kb + 2);

        const uint32_t Ab = sb + s * STAGE_BYTES;
        const uint32_t Bb = Ab + 16384;

        #pragma unroll
        for (int kx = 0; kx < 4; kx++) {
            const int kk = (kx + wid) & 3;
            uint32_t af[4][4], bf[2][4];
            const uint32_t akoff = (uint32_t)(kk * 32 + ((lane >> 4) & 1) * 16);
            #pragma unroll
            for (int mt = 0; mt < 4; mt++)
                ldmx4(af[mt], Ab + SWZ((uint32_t)((arow + mt * 16) * 128) + akoff));
            const uint32_t bkoff = (uint32_t)(kk * 32 + ((lane >> 3) & 1) * 16);
            #pragma unroll
            for (int np = 0; np < 2; np++)
                ldmx4(bf[np], Bb + SWZ((uint32_t)((brow + np * 16) * 128) + bkoff));
            #pragma unroll
            for (int mt = 0; mt < 4; mt++)
                #pragma unroll
                for (int nt = 0; nt < 4; nt++)
                    mma_f16(acc[mt][nt], af[mt], &bf[nt >> 1][(nt & 1) * 2]);
        }
    }
    __syncthreads();

    float* sf = reinterpret_cast<float*>(smem);
    #pragma unroll
    for (int mt = 0; mt < 4; mt++) {
        int r0 = wm * 64 + mt * 16 + (lane >> 2);
        #pragma unroll
        for (int nt = 0; nt < 4; nt++) {
            int c = wn * 32 + nt * 8 + 2 * (lane & 3);
            sf[r0 * 132 + c]           = acc[mt][nt][0];
            sf[r0 * 132 + c + 1]       = acc[mt][nt][1];
            sf[(r0 + 8) * 132 + c]     = acc[mt][nt][2];
            sf[(r0 + 8) * 132 + c + 1] = acc[mt][nt][3];
        }
    }
    __syncthreads();

    #pragma unroll 1
    for (int it = 0; it < 16; it++) {
        int i2 = it * 256 + tid;
        int row = i2 >> 5, uu = i2 & 31;
        float4 z = *reinterpret_cast<const float4*>(&sf[row * 132 + uu * 4]);
        int n0 = nbase + uu * 4;
        float4 bz = *reinterpret_cast<const float4*>(&g_b2p[n0]);
        float4 o;
        o.x = z.x + bz.x;
        o.y = z.y + bz.y;
        o.z = z.z + bz.z;
        o.w = z.w + bz.w;
        *reinterpret_cast<float4*>(
            &g_logits[(size_t)(mbase + row) * NPAD + n0]) = o;
    }
}

// ---------------- softmax (exp cached in smem) ----------------
__global__ void softmax_kernel(float* __restrict__ out) {
    const int b = blockIdx.x;
    const float* __restrict__ l = g_logits + (size_t)b * NPAD;
    __shared__ float red[256];
    __shared__ float ex[VOCAB_];
    const int tid = threadIdx.x;

    float mval = -1e30f;
    for (int v = tid; v < VOCAB_; v += 256) mval = fmaxf(mval, l[v]);
    red[tid] = mval;
    __syncthreads();
    for (int s = 128; s > 0; s >>= 1) {
        if (tid < s) red[tid] = fmaxf(red[tid], red[tid + s]);
        __syncthreads();
    }
    float mx = red[0];
    __syncthreads();

    float sum = 0.f;
    for (int v = tid; v < VOCAB_; v += 256) {
        float e = expf(l[v] - mx);
        ex[v] = e;
        sum += e;
    }
    red[tid] = sum;
    __syncthreads();
    for (int s = 128; s > 0; s >>= 1) {
        if (tid < s) red[tid] += red[tid + s];
        __syncthreads();
    }
    float inv = 1.f / red[0];
    for (int v = tid; v < VOCAB_; v += 256)
        out[(size_t)b * VOCAB_ + v] = ex[v] * inv;
}

// ---------------- launch ----------------
extern "C" void kernel_launch(void* const* d_in, const int* in_sizes, int n_in,
                              void* d_out, int out_size) {
    const float* x      = (const float*)d_in[0];
    const float* kernel = (const float*)d_in[1];
    const float* rec    = (const float*)d_in[2];
    const float* bias   = (const float*)d_in[3];
    const float* w2     = (const float*)d_in[4];
    const float* b2     = (const float*)d_in[5];
    float* out = (float*)d_out;

    cudaFuncSetAttribute(lstm_persistent,
                         cudaFuncAttributeMaxDynamicSharedMemorySize, SMEM_BYTES);
    cudaFuncSetAttribute(dense2_mma,
                         cudaFuncAttributeMaxDynamicSharedMemorySize, SMEM_BYTES);

    prep_weights<<<2048, 256>>>(kernel, rec, bias, w2, b2);
    prep_x<<<2048, 256>>>(x);
    zero_state<<<2048, 256>>>();

    lstm_persistent<<<NCTA, 256, SMEM_BYTES>>>();

    dense2_mma<<<dim3(NPAD / 128, B_ / 128), 256, SMEM_BYTES>>>(SEQ_ & 1);
    softmax_kernel<<<B_, 256>>>(out);
}

// round 16
// speedup vs baseline: 1.1976x; 1.0229x over previous
#include <cuda_runtime.h>
#include <cuda_fp16.h>
#include <math.h>
#include <stdint.h>

#define B_      4096
#define SEQ_    59
#define FEAT_   64
#define U_      1024
#define VOCAB_  578
#define NPAD    640
#define KTOT    1088            // U_ + FEAT_
#define N4U     4096            // 4*U_
#define XROW    (SEQ_*FEAT_)

#define KBLK        64
#define NKB         17          // KTOT / KBLK
#define NSTAGE      3
#define STAGE_BYTES 32768       // A 16K | B 16K
#define SMEM_BYTES  (NSTAGE * STAGE_BYTES)   // 98304 per CTA, 2 CTAs/SM
#define NCTA        296         // 2 x 148: all co-resident
#define NTILES      1024        // 32 mgroups x 32 ntiles
#define TOT_TILES   (SEQ_ * NTILES)

// ---------------- device scratch ----------------
__device__ __half g_Wt[(size_t)N4U * KTOT];      // [n][k], n = 4u+g permuted
__device__ float  g_biasp[N4U];
__device__ __half g_h16[2][(size_t)B_ * U_];
__device__ float  g_c[(size_t)B_ * U_];
__device__ __half g_x16[(size_t)SEQ_ * B_ * FEAT_]; // [t][b][f]
__device__ __half g_w2t[(size_t)NPAD * U_];      // [n][k] fp16
__device__ float  g_b2p[NPAD];
__device__ float  g_logits[(size_t)B_ * NPAD];
__device__ int    g_cnt[SEQ_ * 32];              // per (t, mgroup) finished n-tiles
__device__ unsigned g_tile;                      // dynamic tile counter

// ---------------- helpers ----------------
__device__ __forceinline__ uint32_t s2u(const void* p) {
    uint32_t a;
    asm("{ .reg .u64 t; cvta.to.shared.u64 t, %1; cvt.u32.u64 %0, t; }"
        : "=r"(a) : "l"(p));
    return a;
}
__device__ __forceinline__ void cp16(uint32_t saddr, const void* g) {
    asm volatile("cp.async.cg.shared.global [%0], [%1], 16;"
                 :: "r"(saddr), "l"(g));
}
__device__ __forceinline__ void ldmx4(uint32_t* r, uint32_t addr) {
    asm volatile("ldmatrix.sync.aligned.m8n8.x4.shared.b16 {%0,%1,%2,%3}, [%4];"
                 : "=r"(r[0]), "=r"(r[1]), "=r"(r[2]), "=r"(r[3]) : "r"(addr));
}
__device__ __forceinline__ void mma_f16(float* d, const uint32_t* a,
                                        const uint32_t* b) {
    asm volatile(
        "mma.sync.aligned.m16n8k16.row.col.f32.f16.f16.f32 "
        "{%0,%1,%2,%3}, {%4,%5,%6,%7}, {%8,%9}, {%0,%1,%2,%3};"
        : "+f"(d[0]), "+f"(d[1]), "+f"(d[2]), "+f"(d[3])
        : "r"(a[0]), "r"(a[1]), "r"(a[2]), "r"(a[3]), "r"(b[0]), "r"(b[1]));
}
#define SWZ(o) ((o) ^ (((o) >> 3) & 0x70))

__device__ __forceinline__ float fast_sigmoid(float x) {
    return __fdividef(1.f, 1.f + __expf(-x));
}
__device__ __forceinline__ float fast_tanh(float x) {
    float e = __expf(2.f * x);
    return 1.f - __fdividef(2.f, e + 1.f);
}

// ---------------- prep kernels ----------------
__global__ void prep_weights(const float* __restrict__ kernel,
                             const float* __restrict__ rec,
                             const float* __restrict__ bias,
                             const float* __restrict__ w2,
                             const float* __restrict__ b2) {
    int stride = gridDim.x * blockDim.x;
    int idx = blockIdx.x * blockDim.x + threadIdx.x;
    for (size_t i = idx; i < (size_t)N4U * KTOT; i += stride) {
        int n = (int)(i / KTOT), k = (int)(i % KTOT);
        int u = n >> 2, g = n & 3;
        int src = g * U_ + u;
        float v = (k < U_) ? rec[(size_t)k * N4U + src]
                           : kernel[(size_t)(k - U_) * N4U + src];
        g_Wt[i] = __float2half(v);
    }
    for (int n = idx; n < N4U; n += stride) {
        int u = n >> 2, g = n & 3;
        g_biasp[n] = bias[g * U_ + u];
    }
    // w2 transposed fp16: [NPAD][U_]
    for (size_t i = idx; i < (size_t)NPAD * U_; i += stride) {
        int n = (int)(i / U_), k = (int)(i % U_);
        g_w2t[i] = __float2half((n < VOCAB_) ? w2[(size_t)k * VOCAB_ + n] : 0.f);
    }
    for (int v = idx; v < NPAD; v += stride)
        g_b2p[v] = (v < VOCAB_) ? b2[v] : 0.f;
}

__global__ void prep_x(const float* __restrict__ x) {
    int stride = gridDim.x * blockDim.x;
    int idx = blockIdx.x * blockDim.x + threadIdx.x;
    for (size_t i = idx; i < (size_t)SEQ_ * B_ * FEAT_; i += stride) {
        int t = (int)(i / ((size_t)B_ * FEAT_));
        int r = (int)((i / FEAT_) % B_);
        int f = (int)(i % FEAT_);
        g_x16[i] = __float2half(x[(size_t)r * XROW + t * FEAT_ + f]);
    }
}

__global__ void zero_state() {
    int stride = gridDim.x * blockDim.x;
    int idx = blockIdx.x * blockDim.x + threadIdx.x;
    const __half z = __float2half(0.f);
    for (size_t i = idx; i < (size_t)B_ * U_; i += stride) {
        g_h16[0][i] = z;
        g_c[i] = 0.f;
    }
    for (int i = idx; i < SEQ_ * 32; i += stride)
        g_cnt[i] = 0;
    if (idx == 0) g_tile = 0u;
}

// ---------------- persistent LSTM: dynamic tile scheduler -----------------
// CTA 128x128, 8 warps (2M x 4N), warp tile 64x32, K-chunk 64,
// 3-stage cp.async, per-warp kk rotation, 296 CTAs (2/SM, all resident).
// Tiles claimed via global atomic counter (monotonic: all step-t tiles are
// dispensed before any t+1 tile). Cross-step deps (h RAW/WAR and c RAW) via
// per-(t,mg) release-counter / acquire-wait. x-block loaded first (no dep),
// coarse wait overlapped behind it.
__global__ void __launch_bounds__(256, 2)
lstm_persistent() {
    extern __shared__ __align__(1024) char smem[];
    __shared__ unsigned s_tile;
    const uint32_t sb = s2u(smem);
    const int tid = threadIdx.x;
    const int lane = tid & 31, wid = tid >> 5;
    const int wm = wid & 1, wn = wid >> 1;

    const int arow = wm * 64 + (lane & 15);
    const int brow = wn * 32 + (lane & 7) + ((lane >> 4) & 1) * 8;

    #pragma unroll 1
    while (true) {
        if (tid == 0) s_tile = atomicAdd(&g_tile, 1u);
        __syncthreads();
        const unsigned tile = s_tile;
        __syncthreads();           // protect s_tile before next overwrite
        if (tile >= TOT_TILES) break;

        const int t   = (int)(tile >> 10);
        const int idx = (int)(tile & 1023);
        const int mg = idx >> 5;
        const int mbase = mg * 128;
        const int nbase = (idx & 31) * 128;

        const __half* __restrict__ hh = g_h16[t & 1];
        __half* __restrict__ oh = g_h16[(t & 1) ^ 1];

        float acc[4][4][4];
        #pragma unroll
        for (int i = 0; i < 4; i++)
            #pragma unroll
            for (int j = 0; j < 4; j++)
                #pragma unroll
                for (int q = 0; q < 4; q++) acc[i][j][q] = 0.f;

        auto loadStage = [&](int s, int kb) {
            const uint32_t base = sb + s * STAGE_BYTES;
            #pragma unroll
            for (int it = 0; it < 4; it++) {
                int i2 = tid + it * 256;
                int row = i2 >> 3, cc = i2 & 7;
                uint32_t sw = SWZ((uint32_t)(row * 128 + cc * 16));
                const __half* ga;
                if (kb < 16)
                    ga = hh + (size_t)(mbase + row) * U_ + kb * KBLK + cc * 8;
                else
                    ga = g_x16 + ((size_t)t * B_ + mbase + row) * FEAT_ + cc * 8;
                cp16(base + sw, ga);
                size_t ob = (size_t)(nbase + row) * KTOT + kb * KBLK + cc * 8;
                cp16(base + 16384 + sw, g_Wt + ob);
            }
            asm volatile("cp.async.commit_group;" ::: "memory");
        };

        // prologue: x block first (no cross-step dep) ...
        loadStage(0, 16);
        // ... then the coarse wait, overlapped behind the x prefetch
        if (t > 0) {
            if (tid == 0) {
                const int* cp = &g_cnt[(t - 1) * 32 + mg];
                int v;
                do {
                    asm volatile("ld.acquire.gpu.global.s32 %0, [%1];"
                                 : "=r"(v) : "l"(cp) : "memory");
                    if (v < 32) __nanosleep(64);
                } while (v < 32);
            }
            __syncthreads();
        }
        loadStage(1, 0);

        // j-th compute block: kb = (j==0) ? 16 : j-1
        #pragma unroll 1
        for (int j = 0; j < NKB; j++) {
            if (j < NKB - 1) asm volatile("cp.async.wait_group 1;" ::: "memory");
            else            asm volatile("cp.async.wait_group 0;" ::: "memory");
            __syncthreads();

            // prefetch block j+2 (kb = j+1) into stage (j+2)%3
            if (j + 2 < NKB) loadStage((j + 2) % 3, j + 1);

            const uint32_t Ab = sb + (j % 3) * STAGE_BYTES;
            const uint32_t Bb = Ab + 16384;

            #pragma unroll
            for (int kx = 0; kx < 4; kx++) {
                const int kk = (kx + wid) & 3;   // per-warp phase rotation
                uint32_t af[4][4], bf[2][4];
                const uint32_t akoff = (uint32_t)(kk * 32 + ((lane >> 4) & 1) * 16);
                #pragma unroll
                for (int mt = 0; mt < 4; mt++)
                    ldmx4(af[mt], Ab + SWZ((uint32_t)((arow + mt * 16) * 128) + akoff));
                const uint32_t bkoff = (uint32_t)(kk * 32 + ((lane >> 3) & 1) * 16);
                #pragma unroll
                for (int np = 0; np < 2; np++)
                    ldmx4(bf[np], Bb + SWZ((uint32_t)((brow + np * 16) * 128) + bkoff));
                #pragma unroll
                for (int mt = 0; mt < 4; mt++)
                    #pragma unroll
                    for (int nt = 0; nt < 4; nt++)
                        mma_f16(acc[mt][nt], af[mt], &bf[nt >> 1][(nt & 1) * 2]);
            }
        }
        __syncthreads();

        // ---- epilogue: stage accums to smem [128][132], gate math ----
        float* sf = reinterpret_cast<float*>(smem);
        #pragma unroll
        for (int mt = 0; mt < 4; mt++) {
            int r0 = wm * 64 + mt * 16 + (lane >> 2);
            #pragma unroll
            for (int nt = 0; nt < 4; nt++) {
                int c = wn * 32 + nt * 8 + 2 * (lane & 3);
                sf[r0 * 132 + c]           = acc[mt][nt][0];
                sf[r0 * 132 + c + 1]       = acc[mt][nt][1];
                sf[(r0 + 8) * 132 + c]     = acc[mt][nt][2];
                sf[(r0 + 8) * 132 + c + 1] = acc[mt][nt][3];
            }
        }
        __syncthreads();

        #pragma unroll 1
        for (int it = 0; it < 16; it++) {
            int i2 = it * 256 + tid;
            int row = i2 >> 5, uu = i2 & 31;
            float4 z = *reinterpret_cast<const float4*>(&sf[row * 132 + uu * 4]);
            int n0 = nbase + uu * 4;
            float4 bz = *reinterpret_cast<const float4*>(&g_biasp[n0]);
            float ig = fast_sigmoid(z.x + bz.x);
            float fg = fast_sigmoid(z.y + bz.y);
            float gg = fast_tanh(z.z + bz.z);
            float og = fast_sigmoid(z.w + bz.w);
            size_t ci = (size_t)(mbase + row) * U_ + (n0 >> 2);
            float cn = fg * g_c[ci] + ig * gg;
            g_c[ci] = cn;
            float hv = og * fast_tanh(cn);
            oh[ci] = __float2half(hv);
        }

        // ---- publish: release-add this tile to (t, mg) counter ----
        __syncthreads();
        if (tid == 0) {
            __threadfence();
            atomicAdd(&g_cnt[t * 32 + mg], 1);
        }
    }
}

// ---------------- final dense: fp16 mma GEMM, logits = h @ w2 + b2 --------
__global__ void __launch_bounds__(256, 2)
dense2_mma(int h_idx) {
    extern __shared__ __align__(1024) char smem[];
    const uint32_t sb = s2u(smem);
    const int tid = threadIdx.x;
    const int lane = tid & 31, wid = tid >> 5;
    const int wm = wid & 1, wn = wid >> 1;
    const int mbase = blockIdx.y * 128;
    const int nbase = blockIdx.x * 128;

    const __half* __restrict__ A = g_h16[h_idx];

    float acc[4][4][4];
    #pragma unroll
    for (int i = 0; i < 4; i++)
        #pragma unroll
        for (int j = 0; j < 4; j++)
            #pragma unroll
            for (int q = 0; q < 4; q++) acc[i][j][q] = 0.f;

    auto loadStage = [&](int s, int kb) {
        const uint32_t base = sb + s * STAGE_BYTES;
        #pragma unroll
        for (int it = 0; it < 4; it++) {
            int i2 = tid + it * 256;
            int row = i2 >> 3, cc = i2 & 7;
            uint32_t sw = SWZ((uint32_t)(row * 128 + cc * 16));
            cp16(base + sw, A + (size_t)(mbase + row) * U_ + kb * KBLK + cc * 8);
            cp16(base + 16384 + sw,
                 g_w2t + (size_t)(nbase + row) * U_ + kb * KBLK + cc * 8);
        }
        asm volatile("cp.async.commit_group;" ::: "memory");
    };

    loadStage(0, 0);
    loadStage(1, 1);

    const int arow = wm * 64 + (lane & 15);
    const int brow = wn * 32 + (lane & 7) + ((lane >> 4) & 1) * 8;

    const int NKD = U_ / KBLK;   // 16
    #pragma unroll 1
    for (int kb = 0; kb < NKD; kb++) {
        const int s = kb % 3;
        if (kb < NKD - 1) asm volatile("cp.async.wait_group 1;" ::: "memory");
        else             asm volatile("cp.async.wait_group 0;" ::: "memory");
        __syncthreads();

        if (kb + 2 < NKD) loadStage((kb + 2) % 3, kb + 2);

        const uint32_t Ab = sb + s * STAGE_BYTES;
        const uint32_t Bb = Ab + 16384;

        #pragma unroll
        for (int kx = 0; kx < 4; kx++) {
            const int kk = (kx + wid) & 3;
            uint32_t af[4][4], bf[2][4];
            const uint32_t akoff = (uint32_t)(kk * 32 + ((lane >> 4) & 1) * 16);
            #pragma unroll
            for (int mt = 0; mt < 4; mt++)
                ldmx4(af[mt], Ab + SWZ((uint32_t)((arow + mt * 16) * 128) + akoff));
            const uint32_t bkoff = (uint32_t)(kk * 32 + ((lane >> 3) & 1) * 16);
            #pragma unroll
            for (int np = 0; np < 2; np++)
                ldmx4(bf[np], Bb + SWZ((uint32_t)((brow + np * 16) * 128) + bkoff));
            #pragma unroll
            for (int mt = 0; mt < 4; mt++)
                #pragma unroll
                for (int nt = 0; nt < 4; nt++)
                    mma_f16(acc[mt][nt], af[mt], &bf[nt >> 1][(nt & 1) * 2]);
        }
    }
    __syncthreads();

    float* sf = reinterpret_cast<float*>(smem);
    #pragma unroll
    for (int mt = 0; mt < 4; mt++) {
        int r0 = wm * 64 + mt * 16 + (lane >> 2);
        #pragma unroll
        for (int nt = 0; nt < 4; nt++) {
            int c = wn * 32 + nt * 8 + 2 * (lane & 3);
            sf[r0 * 132 + c]           = acc[mt][nt][0];
            sf[r0 * 132 + c + 1]       = acc[mt][nt][1];
            sf[(r0 + 8) * 132 + c]     = acc[mt][nt][2];
            sf[(r0 + 8) * 132 + c + 1] = acc[mt][nt][3];
        }
    }
    __syncthreads();

    #pragma unroll 1
    for (int it = 0; it < 16; it++) {
        int i2 = it * 256 + tid;
        int row = i2 >> 5, uu = i2 & 31;
        float4 z = *reinterpret_cast<const float4*>(&sf[row * 132 + uu * 4]);
        int n0 = nbase + uu * 4;
        float4 bz = *reinterpret_cast<const float4*>(&g_b2p[n0]);
        float4 o;
        o.x = z.x + bz.x;
        o.y = z.y + bz.y;
        o.z = z.z + bz.z;
        o.w = z.w + bz.w;
        *reinterpret_cast<float4*>(
            &g_logits[(size_t)(mbase + row) * NPAD + n0]) = o;
    }
}

// ---------------- softmax (exp cached in smem) ----------------
__global__ void softmax_kernel(float* __restrict__ out) {
    const int b = blockIdx.x;
    const float* __restrict__ l = g_logits + (size_t)b * NPAD;
    __shared__ float red[256];
    __shared__ float ex[VOCAB_];
    const int tid = threadIdx.x;

    float mval = -1e30f;
    for (int v = tid; v < VOCAB_; v += 256) mval = fmaxf(mval, l[v]);
    red[tid] = mval;
    __syncthreads();
    for (int s = 128; s > 0; s >>= 1) {
        if (tid < s) red[tid] = fmaxf(red[tid], red[tid + s]);
        __syncthreads();
    }
    float mx = red[0];
    __syncthreads();

    float sum = 0.f;
    for (int v = tid; v < VOCAB_; v += 256) {
        float e = expf(l[v] - mx);
        ex[v] = e;
        sum += e;
    }
    red[tid] = sum;
    __syncthreads();
    for (int s = 128; s > 0; s >>= 1) {
        if (tid < s) red[tid] += red[tid + s];
        __syncthreads();
    }
    float inv = 1.f / red[0];
    for (int v = tid; v < VOCAB_; v += 256)
        out[(size_t)b * VOCAB_ + v] = ex[v] * inv;
}

// ---------------- launch ----------------
extern "C" void kernel_launch(void* const* d_in, const int* in_sizes, int n_in,
                              void* d_out, int out_size) {
    const float* x      = (const float*)d_in[0];
    const float* kernel = (const float*)d_in[1];
    const float* rec    = (const float*)d_in[2];
    const float* bias   = (const float*)d_in[3];
    const float* w2     = (const float*)d_in[4];
    const float* b2     = (const float*)d_in[5];
    float* out = (float*)d_out;

    cudaFuncSetAttribute(lstm_persistent,
                         cudaFuncAttributeMaxDynamicSharedMemorySize, SMEM_BYTES);
    cudaFuncSetAttribute(dense2_mma,
                         cudaFuncAttributeMaxDynamicSharedMemorySize, SMEM_BYTES);

    prep_weights<<<2048, 256>>>(kernel, rec, bias, w2, b2);
    prep_x<<<2048, 256>>>(x);
    zero_state<<<2048, 256>>>();

    lstm_persistent<<<NCTA, 256, SMEM_BYTES>>>();

    dense2_mma<<<dim3(NPAD / 128, B_ / 128), 256, SMEM_BYTES>>>(SEQ_ & 1);
    softmax_kernel<<<B_, 256>>>(out);
}

// round 17
// speedup vs baseline: 1.2132x; 1.0131x over previous
#include <cuda_runtime.h>
#include <cuda_fp16.h>
#include <math.h>
#include <stdint.h>

#define B_      4096
#define SEQ_    59
#define FEAT_   64
#define U_      1024
#define VOCAB_  578
#define NPAD    640
#define KTOT    1088            // U_ + FEAT_
#define N4U     4096            // 4*U_
#define XROW    (SEQ_*FEAT_)

#define KBLK        64
#define NKB         17          // KTOT / KBLK
#define NSTAGE      3
#define STAGE_BYTES 32768       // A 16K | B 16K
#define SMEM_BYTES  (NSTAGE * STAGE_BYTES)   // 98304 per CTA, 2 CTAs/SM
#define NCTA        296         // 2 x 148: all co-resident
#define NTILES      1024        // 32 mgroups x 32 ntiles
#define TOT_TILES   (SEQ_ * NTILES)
#define DENSE_TILES 160         // 32 mgroups x 5 n-tiles (NPAD/128)
#define ALL_TILES   (TOT_TILES + DENSE_TILES)

// ---------------- device scratch ----------------
__device__ __half g_Wt[(size_t)N4U * KTOT];      // [n][k], n = 4u+g permuted
__device__ float  g_biasp[N4U];
__device__ __half g_h16[2][(size_t)B_ * U_];
__device__ float  g_c[(size_t)B_ * U_];
__device__ __half g_x16[(size_t)SEQ_ * B_ * FEAT_]; // [t][b][f]
__device__ __half g_w2t[(size_t)NPAD * U_];      // [n][k] fp16
__device__ float  g_b2p[NPAD];
__device__ float  g_logits[(size_t)B_ * NPAD];
__device__ int    g_cnt[SEQ_ * 32];              // per (t, mgroup) finished n-tiles
__device__ unsigned g_tile;                      // dynamic tile counter

// ---------------- helpers ----------------
__device__ __forceinline__ uint32_t s2u(const void* p) {
    uint32_t a;
    asm("{ .reg .u64 t; cvta.to.shared.u64 t, %1; cvt.u32.u64 %0, t; }"
        : "=r"(a) : "l"(p));
    return a;
}
__device__ __forceinline__ void cp16(uint32_t saddr, const void* g) {
    asm volatile("cp.async.cg.shared.global [%0], [%1], 16;"
                 :: "r"(saddr), "l"(g));
}
__device__ __forceinline__ void ldmx4(uint32_t* r, uint32_t addr) {
    asm volatile("ldmatrix.sync.aligned.m8n8.x4.shared.b16 {%0,%1,%2,%3}, [%4];"
                 : "=r"(r[0]), "=r"(r[1]), "=r"(r[2]), "=r"(r[3]) : "r"(addr));
}
__device__ __forceinline__ void mma_f16(float* d, const uint32_t* a,
                                        const uint32_t* b) {
    asm volatile(
        "mma.sync.aligned.m16n8k16.row.col.f32.f16.f16.f32 "
        "{%0,%1,%2,%3}, {%4,%5,%6,%7}, {%8,%9}, {%0,%1,%2,%3};"
        : "+f"(d[0]), "+f"(d[1]), "+f"(d[2]), "+f"(d[3])
        : "r"(a[0]), "r"(a[1]), "r"(a[2]), "r"(a[3]), "r"(b[0]), "r"(b[1]));
}
#define SWZ(o) ((o) ^ (((o) >> 3) & 0x70))

__device__ __forceinline__ float fast_sigmoid(float x) {
    return __fdividef(1.f, 1.f + __expf(-x));
}
__device__ __forceinline__ float fast_tanh(float x) {
    float e = __expf(2.f * x);
    return 1.f - __fdividef(2.f, e + 1.f);
}
__device__ __forceinline__ void wait_cnt32(const int* cp) {
    int v;
    do {
        asm volatile("ld.acquire.gpu.global.s32 %0, [%1];"
                     : "=r"(v) : "l"(cp) : "memory");
        if (v < 32) __nanosleep(64);
    } while (v < 32);
}

// ---------------- prep (merged) ----------------
__global__ void prep_all(const float* __restrict__ kernel,
                         const float* __restrict__ rec,
                         const float* __restrict__ bias,
                         const float* __restrict__ w2,
                         const float* __restrict__ b2,
                         const float* __restrict__ x) {
    int stride = gridDim.x * blockDim.x;
    int idx = blockIdx.x * blockDim.x + threadIdx.x;
    for (size_t i = idx; i < (size_t)N4U * KTOT; i += stride) {
        int n = (int)(i / KTOT), k = (int)(i % KTOT);
        int u = n >> 2, g = n & 3;
        int src = g * U_ + u;
        float v = (k < U_) ? rec[(size_t)k * N4U + src]
                           : kernel[(size_t)(k - U_) * N4U + src];
        g_Wt[i] = __float2half(v);
    }
    for (int n = idx; n < N4U; n += stride) {
        int u = n >> 2, g = n & 3;
        g_biasp[n] = bias[g * U_ + u];
    }
    for (size_t i = idx; i < (size_t)NPAD * U_; i += stride) {
        int n = (int)(i / U_), k = (int)(i % U_);
        g_w2t[i] = __float2half((n < VOCAB_) ? w2[(size_t)k * VOCAB_ + n] : 0.f);
    }
    for (int v = idx; v < NPAD; v += stride)
        g_b2p[v] = (v < VOCAB_) ? b2[v] : 0.f;
    for (size_t i = idx; i < (size_t)SEQ_ * B_ * FEAT_; i += stride) {
        int t = (int)(i / ((size_t)B_ * FEAT_));
        int r = (int)((i / FEAT_) % B_);
        int f = (int)(i % FEAT_);
        g_x16[i] = __float2half(x[(size_t)r * XROW + t * FEAT_ + f]);
    }
    const __half z = __float2half(0.f);
    for (size_t i = idx; i < (size_t)B_ * U_; i += stride) {
        g_h16[0][i] = z;
        g_c[i] = 0.f;
    }
    for (int i = idx; i < SEQ_ * 32; i += stride)
        g_cnt[i] = 0;
    if (idx == 0) g_tile = 0u;
}

// ---------------- persistent LSTM + fused dense: dynamic scheduler --------
// Tiles 0..TOT_TILES-1: LSTM step tiles (t, mg, nt). Tiles TOT_TILES..
// ALL_TILES-1: dense tiles (mg, nv) of logits = h_last @ w2t + b2, gated on
// cnt[SEQ-1][mg]==32. Monotonic counter -> all deps point backward.
__global__ void __launch_bounds__(256, 2)
lstm_persistent() {
    extern __shared__ __align__(1024) char smem[];
    __shared__ unsigned s_tile;
    const uint32_t sb = s2u(smem);
    const int tid = threadIdx.x;
    const int lane = tid & 31, wid = tid >> 5;
    const int wm = wid & 1, wn = wid >> 1;

    const int arow = wm * 64 + (lane & 15);
    const int brow = wn * 32 + (lane & 7) + ((lane >> 4) & 1) * 8;

    #pragma unroll 1
    while (true) {
        if (tid == 0) s_tile = atomicAdd(&g_tile, 1u);
        __syncthreads();
        const unsigned tile = s_tile;
        __syncthreads();           // protect s_tile before next overwrite
        if (tile >= ALL_TILES) break;

        float acc[4][4][4];
        #pragma unroll
        for (int i = 0; i < 4; i++)
            #pragma unroll
            for (int j = 0; j < 4; j++)
                #pragma unroll
                for (int q = 0; q < 4; q++) acc[i][j][q] = 0.f;

        if (tile < TOT_TILES) {
            // ================= LSTM tile =================
            const int t   = (int)(tile >> 10);
            const int idx = (int)(tile & 1023);
            const int mg = idx >> 5;
            const int mbase = mg * 128;
            const int nbase = (idx & 31) * 128;

            const __half* __restrict__ hh = g_h16[t & 1];
            __half* __restrict__ oh = g_h16[(t & 1) ^ 1];

            auto loadStage = [&](int s, int kb) {
                const uint32_t base = sb + s * STAGE_BYTES;
                #pragma unroll
                for (int it = 0; it < 4; it++) {
                    int i2 = tid + it * 256;
                    int row = i2 >> 3, cc = i2 & 7;
                    uint32_t sw = SWZ((uint32_t)(row * 128 + cc * 16));
                    const __half* ga;
                    if (kb < 16)
                        ga = hh + (size_t)(mbase + row) * U_ + kb * KBLK + cc * 8;
                    else
                        ga = g_x16 + ((size_t)t * B_ + mbase + row) * FEAT_ + cc * 8;
                    cp16(base + sw, ga);
                    size_t ob = (size_t)(nbase + row) * KTOT + kb * KBLK + cc * 8;
                    cp16(base + 16384 + sw, g_Wt + ob);
                }
                asm volatile("cp.async.commit_group;" ::: "memory");
            };

            // prologue: x block first (no cross-step dep), wait overlapped
            loadStage(0, 16);
            if (t > 0) {
                if (tid == 0) wait_cnt32(&g_cnt[(t - 1) * 32 + mg]);
                __syncthreads();
            }
            loadStage(1, 0);

            #pragma unroll 1
            for (int j = 0; j < NKB; j++) {
                if (j < NKB - 1) asm volatile("cp.async.wait_group 1;" ::: "memory");
                else            asm volatile("cp.async.wait_group 0;" ::: "memory");
                __syncthreads();

                if (j + 2 < NKB) loadStage((j + 2) % 3, j + 1);

                const uint32_t Ab = sb + (j % 3) * STAGE_BYTES;
                const uint32_t Bb = Ab + 16384;

                #pragma unroll
                for (int kx = 0; kx < 4; kx++) {
                    const int kk = (kx + wid) & 3;
                    uint32_t af[4][4], bf[2][4];
                    const uint32_t akoff = (uint32_t)(kk * 32 + ((lane >> 4) & 1) * 16);
                    #pragma unroll
                    for (int mt = 0; mt < 4; mt++)
                        ldmx4(af[mt], Ab + SWZ((uint32_t)((arow + mt * 16) * 128) + akoff));
                    const uint32_t bkoff = (uint32_t)(kk * 32 + ((lane >> 3) & 1) * 16);
                    #pragma unroll
                    for (int np = 0; np < 2; np++)
                        ldmx4(bf[np], Bb + SWZ((uint32_t)((brow + np * 16) * 128) + bkoff));
                    #pragma unroll
                    for (int mt = 0; mt < 4; mt++)
                        #pragma unroll
                        for (int nt = 0; nt < 4; nt++)
                            mma_f16(acc[mt][nt], af[mt], &bf[nt >> 1][(nt & 1) * 2]);
                }
            }
            __syncthreads();

            // epilogue: stage to smem, gate math
            float* sf = reinterpret_cast<float*>(smem);
            #pragma unroll
            for (int mt = 0; mt < 4; mt++) {
                int r0 = wm * 64 + mt * 16 + (lane >> 2);
                #pragma unroll
                for (int nt = 0; nt < 4; nt++) {
                    int c = wn * 32 + nt * 8 + 2 * (lane & 3);
                    sf[r0 * 132 + c]           = acc[mt][nt][0];
                    sf[r0 * 132 + c + 1]       = acc[mt][nt][1];
                    sf[(r0 + 8) * 132 + c]     = acc[mt][nt][2];
                    sf[(r0 + 8) * 132 + c + 1] = acc[mt][nt][3];
                }
            }
            __syncthreads();

            #pragma unroll 1
            for (int it = 0; it < 16; it++) {
                int i2 = it * 256 + tid;
                int row = i2 >> 5, uu = i2 & 31;
                float4 z = *reinterpret_cast<const float4*>(&sf[row * 132 + uu * 4]);
                int n0 = nbase + uu * 4;
                float4 bz = *reinterpret_cast<const float4*>(&g_biasp[n0]);
                float ig = fast_sigmoid(z.x + bz.x);
                float fg = fast_sigmoid(z.y + bz.y);
                float gg = fast_tanh(z.z + bz.z);
                float og = fast_sigmoid(z.w + bz.w);
                size_t ci = (size_t)(mbase + row) * U_ + (n0 >> 2);
                float cn = fg * g_c[ci] + ig * gg;
                g_c[ci] = cn;
                float hv = og * fast_tanh(cn);
                oh[ci] = __float2half(hv);
            }

            __syncthreads();
            if (tid == 0) {
                __threadfence();
                atomicAdd(&g_cnt[t * 32 + mg], 1);
            }
        } else {
            // ================= dense tile =================
            const int d = (int)(tile - TOT_TILES);
            const int mg = d / 5;
            const int mbase = mg * 128;
            const int nbase = (d % 5) * 128;

            const __half* __restrict__ A = g_h16[SEQ_ & 1];

            auto loadStageD = [&](int s, int kb) {
                const uint32_t base = sb + s * STAGE_BYTES;
                #pragma unroll
                for (int it = 0; it < 4; it++) {
                    int i2 = tid + it * 256;
                    int row = i2 >> 3, cc = i2 & 7;
                    uint32_t sw = SWZ((uint32_t)(row * 128 + cc * 16));
                    cp16(base + sw,
                         A + (size_t)(mbase + row) * U_ + kb * KBLK + cc * 8);
                    cp16(base + 16384 + sw,
                         g_w2t + (size_t)(nbase + row) * U_ + kb * KBLK + cc * 8);
                }
                asm volatile("cp.async.commit_group;" ::: "memory");
            };

            // wait for last-step h rows of this mgroup
            if (tid == 0) wait_cnt32(&g_cnt[(SEQ_ - 1) * 32 + mg]);
            __syncthreads();

            loadStageD(0, 0);
            loadStageD(1, 1);

            const int NKD = U_ / KBLK;   // 16
            #pragma unroll 1
            for (int kb = 0; kb < NKD; kb++) {
                if (kb < NKD - 1) asm volatile("cp.async.wait_group 1;" ::: "memory");
                else             asm volatile("cp.async.wait_group 0;" ::: "memory");
                __syncthreads();

                if (kb + 2 < NKD) loadStageD((kb + 2) % 3, kb + 2);

                const uint32_t Ab = sb + (kb % 3) * STAGE_BYTES;
                const uint32_t Bb = Ab + 16384;

                #pragma unroll
                for (int kx = 0; kx < 4; kx++) {
                    const int kk = (kx + wid) & 3;
                    uint32_t af[4][4], bf[2][4];
                    const uint32_t akoff = (uint32_t)(kk * 32 + ((lane >> 4) & 1) * 16);
                    #pragma unroll
                    for (int mt = 0; mt < 4; mt++)
                        ldmx4(af[mt], Ab + SWZ((uint32_t)((arow + mt * 16) * 128) + akoff));
                    const uint32_t bkoff = (uint32_t)(kk * 32 + ((lane >> 3) & 1) * 16);
                    #pragma unroll
                    for (int np = 0; np < 2; np++)
                        ldmx4(bf[np], Bb + SWZ((uint32_t)((brow + np * 16) * 128) + bkoff));
                    #pragma unroll
                    for (int mt = 0; mt < 4; mt++)
                        #pragma unroll
                        for (int nt = 0; nt < 4; nt++)
                            mma_f16(acc[mt][nt], af[mt], &bf[nt >> 1][(nt & 1) * 2]);
                }
            }
            __syncthreads();

            float* sf = reinterpret_cast<float*>(smem);
            #pragma unroll
            for (int mt = 0; mt < 4; mt++) {
                int r0 = wm * 64 + mt * 16 + (lane >> 2);
                #pragma unroll
                for (int nt = 0; nt < 4; nt++) {
                    int c = wn * 32 + nt * 8 + 2 * (lane & 3);
                    sf[r0 * 132 + c]           = acc[mt][nt][0];
                    sf[r0 * 132 + c + 1]       = acc[mt][nt][1];
                    sf[(r0 + 8) * 132 + c]     = acc[mt][nt][2];
                    sf[(r0 + 8) * 132 + c + 1] = acc[mt][nt][3];
                }
            }
            __syncthreads();

            #pragma unroll 1
            for (int it = 0; it < 16; it++) {
                int i2 = it * 256 + tid;
                int row = i2 >> 5, uu = i2 & 31;
                float4 z = *reinterpret_cast<const float4*>(&sf[row * 132 + uu * 4]);
                int n0 = nbase + uu * 4;
                float4 bz = *reinterpret_cast<const float4*>(&g_b2p[n0]);
                float4 o;
                o.x = z.x + bz.x;
                o.y = z.y + bz.y;
                o.z = z.z + bz.z;
                o.w = z.w + bz.w;
                *reinterpret_cast<float4*>(
                    &g_logits[(size_t)(mbase + row) * NPAD + n0]) = o;
            }
            __syncthreads();
        }
    }
}

// ---------------- softmax (exp cached in smem) ----------------
__global__ void softmax_kernel(float* __restrict__ out) {
    const int b = blockIdx.x;
    const float* __restrict__ l = g_logits + (size_t)b * NPAD;
    __shared__ float red[256];
    __shared__ float ex[VOCAB_];
    const int tid = threadIdx.x;

    float mval = -1e30f;
    for (int v = tid; v < VOCAB_; v += 256) mval = fmaxf(mval, l[v]);
    red[tid] = mval;
    __syncthreads();
    for (int s = 128; s > 0; s >>= 1) {
        if (tid < s) red[tid] = fmaxf(red[tid], red[tid + s]);
        __syncthreads();
    }
    float mx = red[0];
    __syncthreads();

    float sum = 0.f;
    for (int v = tid; v < VOCAB_; v += 256) {
        float e = expf(l[v] - mx);
        ex[v] = e;
        sum += e;
    }
    red[tid] = sum;
    __syncthreads();
    for (int s = 128; s > 0; s >>= 1) {
        if (tid < s) red[tid] += red[tid + s];
        __syncthreads();
    }
    float inv = 1.f / red[0];
    for (int v = tid; v < VOCAB_; v += 256)
        out[(size_t)b * VOCAB_ + v] = ex[v] * inv;
}

// ---------------- launch ----------------
extern "C" void kernel_launch(void* const* d_in, const int* in_sizes, int n_in,
                              void* d_out, int out_size) {
    const float* x      = (const float*)d_in[0];
    const float* kernel = (const float*)d_in[1];
    const float* rec    = (const float*)d_in[2];
    const float* bias   = (const float*)d_in[3];
    const float* w2     = (const float*)d_in[4];
    const float* b2     = (const float*)d_in[5];
    float* out = (float*)d_out;

    cudaFuncSetAttribute(lstm_persistent,
                         cudaFuncAttributeMaxDynamicSharedMemorySize, SMEM_BYTES);

    prep_all<<<2048, 256>>>(kernel, rec, bias, w2, b2, x);

    lstm_persistent<<<NCTA, 256, SMEM_BYTES>>>();

    softmax_kernel<<<B_, 256>>>(out);
}